// round 5
// baseline (speedup 1.0000x reference)
#include <cuda_runtime.h>
#include <math.h>
#include <stdint.h>

// Problem dims
#define TT 256
#define BB 64
#define EE 512
#define HH 1024
#define VV 10000
#define MALL (TT*BB)          // 16384
#define NG (4*HH)             // 4096 packed gate columns
#define HREGION ((size_t)MALL*HH)      // 16777216 floats (all_h)
#define YBASE   ((size_t)2*MALL*HH)    // 33554432 floats (start of all_y)

// Scratch (device globals: no allocations allowed)
__device__ float g_Xg[(size_t)MALL * NG];   // 268 MB: per-(t,b) x-contribution + bias, packed gate order
__device__ float g_Whp[(size_t)HH * NG];    // 16.8 MB: packed recurrent weights [k][4j+g]
__device__ float g_Wxp[(size_t)EE * NG];    // 8.4 MB: packed input weights
__device__ float g_bgp[NG];

__device__ __forceinline__ unsigned f2tf(float x){
    unsigned u; asm("cvt.rna.tf32.f32 %0, %1;" : "=r"(u) : "f"(x)); return u;
}

__device__ __forceinline__ void mma_tf32(float* c, const unsigned* a, const unsigned* b){
    asm("mma.sync.aligned.m16n8k8.row.col.f32.tf32.tf32.f32 "
        "{%0,%1,%2,%3},{%4,%5,%6,%7},{%8,%9},{%0,%1,%2,%3};"
        : "+f"(c[0]), "+f"(c[1]), "+f"(c[2]), "+f"(c[3])
        : "r"(a[0]), "r"(a[1]), "r"(a[2]), "r"(a[3]), "r"(b[0]), "r"(b[1]));
}

// ---------------------------------------------------------------------------
// Pack gate weights/bias into interleaved layout: col p = 4*j + gate (f,i,c,o)
// W rows [0,H) multiply h (hx = [h, x]); rows [H, H+E) multiply x_emb.
// ---------------------------------------------------------------------------
__global__ void pack_kernel(const float* __restrict__ Wf, const float* __restrict__ Wi,
                            const float* __restrict__ Wc, const float* __restrict__ Wo,
                            const float* __restrict__ bf, const float* __restrict__ bi,
                            const float* __restrict__ bc, const float* __restrict__ bo){
    int stride = gridDim.x * blockDim.x;
    int idx = blockIdx.x * blockDim.x + threadIdx.x;
    const int total = (EE + HH) * HH;
    for (int i = idx; i < total; i += stride){
        int k = i >> 10;          // / HH
        int j = i & (HH - 1);
        float vf = Wf[i], vi = Wi[i], vc = Wc[i], vo = Wo[i];
        int p = j << 2;
        if (k < HH){
            float* d = g_Whp + (size_t)k * NG + p;
            d[0] = vf; d[1] = vi; d[2] = vc; d[3] = vo;
        } else {
            float* d = g_Wxp + (size_t)(k - HH) * NG + p;
            d[0] = vf; d[1] = vi; d[2] = vc; d[3] = vo;
        }
    }
    for (int j = idx; j < HH; j += stride){
        g_bgp[4*j+0] = bf[j]; g_bgp[4*j+1] = bi[j];
        g_bgp[4*j+2] = bc[j]; g_bgp[4*j+3] = bo[j];
    }
}

// ---------------------------------------------------------------------------
// GEMM A: g_Xg[m, p] = sum_k emb[x[m], k] * g_Wxp[k, p] + g_bgp[p]
// M=16384, N=4096, K=512. Block 128x128, Ktile 32, 256 thr (8 warps 2x4).
// ---------------------------------------------------------------------------
__global__ __launch_bounds__(256) void gemm_xproj(const int* __restrict__ x,
                                                  const float* __restrict__ emb){
    __shared__ float As[128][36];
    __shared__ float Bs[32][132];
    const int m0 = blockIdx.y << 7;
    const int n0 = blockIdx.x << 7;
    const int tid = threadIdx.x;
    const int w = tid >> 5, lane = tid & 31;
    const int g = lane >> 2, qi = lane & 3;
    const int wm = (w & 1) << 6, wn = (w >> 1) << 5;

    float acc[4][4][4];
#pragma unroll
    for (int a=0;a<4;++a)
#pragma unroll
    for (int b=0;b<4;++b)
#pragma unroll
    for (int c2=0;c2<4;++c2) acc[a][b][c2] = 0.f;

    int arow[4], akv[4];
    const float* aptr[4];
#pragma unroll
    for (int q=0;q<4;++q){
        int fi = tid + (q<<8);
        arow[q] = fi >> 3; akv[q] = fi & 7;
        aptr[q] = emb + (size_t)x[m0 + arow[q]] * EE + (akv[q]<<2);
    }
    int bkk[4], bnv[4];
    const float* bptr[4];
#pragma unroll
    for (int q=0;q<4;++q){
        int fi = tid + (q<<8);
        bkk[q] = fi >> 5; bnv[q] = fi & 31;
        bptr[q] = g_Wxp + (size_t)bkk[q]*NG + n0 + (bnv[q]<<2);
    }
    float4 ar[4], br[4];
#pragma unroll
    for (int q=0;q<4;++q) ar[q] = *(const float4*)aptr[q];
#pragma unroll
    for (int q=0;q<4;++q) br[q] = *(const float4*)bptr[q];

    const int KT = EE/32;  // 16
    for (int kt = 0; kt < KT; ++kt){
#pragma unroll
        for (int q=0;q<4;++q){
            uint4 u; u.x=f2tf(ar[q].x); u.y=f2tf(ar[q].y); u.z=f2tf(ar[q].z); u.w=f2tf(ar[q].w);
            *reinterpret_cast<uint4*>(&As[arow[q]][akv[q]<<2]) = u;
        }
#pragma unroll
        for (int q=0;q<4;++q){
            uint4 u; u.x=f2tf(br[q].x); u.y=f2tf(br[q].y); u.z=f2tf(br[q].z); u.w=f2tf(br[q].w);
            *reinterpret_cast<uint4*>(&Bs[bkk[q]][bnv[q]<<2]) = u;
        }
        __syncthreads();
        if (kt+1 < KT){
#pragma unroll
            for (int q=0;q<4;++q) ar[q] = *(const float4*)(aptr[q] + (kt+1)*32);
#pragma unroll
            for (int q=0;q<4;++q) br[q] = *(const float4*)(bptr[q] + (size_t)(kt+1)*32*NG);
        }
#pragma unroll
        for (int ks=0; ks<4; ++ks){
            const int kb = ks<<3;
            unsigned af[4][4];
#pragma unroll
            for (int mf=0; mf<4; ++mf){
                int r = wm + (mf<<4) + g;
                af[mf][0] = __float_as_uint(As[r  ][kb+qi]);
                af[mf][1] = __float_as_uint(As[r+8][kb+qi]);
                af[mf][2] = __float_as_uint(As[r  ][kb+qi+4]);
                af[mf][3] = __float_as_uint(As[r+8][kb+qi+4]);
            }
            unsigned bfr[4][2];
#pragma unroll
            for (int nf=0; nf<4; ++nf){
                int cc = wn + (nf<<3) + g;
                bfr[nf][0] = __float_as_uint(Bs[kb+qi  ][cc]);
                bfr[nf][1] = __float_as_uint(Bs[kb+qi+4][cc]);
            }
#pragma unroll
            for (int mf=0; mf<4; ++mf)
#pragma unroll
            for (int nf=0; nf<4; ++nf)
                mma_tf32(acc[mf][nf], af[mf], bfr[nf]);
        }
        __syncthreads();
    }
#pragma unroll
    for (int mf=0; mf<4; ++mf){
        int r0 = m0 + wm + (mf<<4) + g;
#pragma unroll
        for (int nf=0; nf<4; ++nf){
            int col = n0 + wn + (nf<<3) + (qi<<1);
            float b0 = g_bgp[col], b1 = g_bgp[col+1];
            float* d0 = g_Xg + (size_t)r0*NG + col;
            float* d1 = g_Xg + (size_t)(r0+8)*NG + col;
            d0[0] = acc[mf][nf][0] + b0;
            d0[1] = acc[mf][nf][1] + b1;
            d1[0] = acc[mf][nf][2] + b0;
            d1[1] = acc[mf][nf][3] + b1;
        }
    }
}

// ---------------------------------------------------------------------------
// Step kernel: one LSTM timestep. G = h_{t-1} @ Whp + Xg[t]; activations;
// c_t, h_t written into d_out regions. Block owns 32 packed cols (8 hidden
// units) x 64 batch rows. 128 threads, 4 warps (warp w: cols w*8..w*8+7).
// ---------------------------------------------------------------------------
__global__ __launch_bounds__(128) void step_kernel(int t, const float* __restrict__ h0,
                                                   const float* __restrict__ c0,
                                                   float* __restrict__ out){
    __shared__ float Hs[64][36];
    __shared__ float Ws[32][36];
    __shared__ float Gs[64][33];
    const int p0 = blockIdx.x << 5;
    const int tid = threadIdx.x;
    const int w = tid >> 5, lane = tid & 31;
    const int g = lane >> 2, qi = lane & 3;

    const float* hprev = (t == 0) ? h0 : out + (size_t)(t-1)*(BB*HH);
    const float* cprev = (t == 0) ? c0 : out + HREGION + (size_t)(t-1)*(BB*HH);
    float* hout = out + (size_t)t*(BB*HH);
    float* cout = out + HREGION + (size_t)t*(BB*HH);

    float acc[4][4];
#pragma unroll
    for (int a=0;a<4;++a)
#pragma unroll
    for (int b=0;b<4;++b) acc[a][b] = 0.f;

    int arow[4], akv[4];
    const float* aptr[4];
#pragma unroll
    for (int q=0;q<4;++q){
        int fi = tid + (q<<7);
        arow[q] = fi >> 3; akv[q] = fi & 7;
        aptr[q] = hprev + (size_t)arow[q]*HH + (akv[q]<<2);
    }
    int bkk[2], bnv[2];
    const float* bptr[2];
#pragma unroll
    for (int q=0;q<2;++q){
        int fi = tid + (q<<7);
        bkk[q] = fi >> 3; bnv[q] = fi & 7;
        bptr[q] = g_Whp + (size_t)bkk[q]*NG + p0 + (bnv[q]<<2);
    }
    float4 ar[4], br[2];
#pragma unroll
    for (int q=0;q<4;++q) ar[q] = *(const float4*)aptr[q];
#pragma unroll
    for (int q=0;q<2;++q) br[q] = *(const float4*)bptr[q];

    const int KT = HH/32;  // 32
    for (int kt = 0; kt < KT; ++kt){
#pragma unroll
        for (int q=0;q<4;++q){
            uint4 u; u.x=f2tf(ar[q].x); u.y=f2tf(ar[q].y); u.z=f2tf(ar[q].z); u.w=f2tf(ar[q].w);
            *reinterpret_cast<uint4*>(&Hs[arow[q]][akv[q]<<2]) = u;
        }
#pragma unroll
        for (int q=0;q<2;++q){
            uint4 u; u.x=f2tf(br[q].x); u.y=f2tf(br[q].y); u.z=f2tf(br[q].z); u.w=f2tf(br[q].w);
            *reinterpret_cast<uint4*>(&Ws[bkk[q]][bnv[q]<<2]) = u;
        }
        __syncthreads();
        if (kt+1 < KT){
#pragma unroll
            for (int q=0;q<4;++q) ar[q] = *(const float4*)(aptr[q] + (kt+1)*32);
#pragma unroll
            for (int q=0;q<2;++q) br[q] = *(const float4*)(bptr[q] + (size_t)(kt+1)*32*NG);
        }
#pragma unroll
        for (int ks=0; ks<4; ++ks){
            const int kb = ks<<3;
            unsigned bfr[2];
            int cc = (w<<3) + g;
            bfr[0] = __float_as_uint(Ws[kb+qi  ][cc]);
            bfr[1] = __float_as_uint(Ws[kb+qi+4][cc]);
#pragma unroll
            for (int mf=0; mf<4; ++mf){
                int r = (mf<<4) + g;
                unsigned af[4];
                af[0] = __float_as_uint(Hs[r  ][kb+qi]);
                af[1] = __float_as_uint(Hs[r+8][kb+qi]);
                af[2] = __float_as_uint(Hs[r  ][kb+qi+4]);
                af[3] = __float_as_uint(Hs[r+8][kb+qi+4]);
                mma_tf32(acc[mf], af, bfr);
            }
        }
        __syncthreads();
    }

    // add Xg (bias folded in) and stage G in shared memory
    const int m_base = t * BB;
#pragma unroll
    for (int mf=0; mf<4; ++mf){
        int r = (mf<<4) + g;
        int col = (w<<3) + (qi<<1);
        const float* xg0 = g_Xg + (size_t)(m_base + r)*NG + p0 + col;
        const float* xg1 = g_Xg + (size_t)(m_base + r + 8)*NG + p0 + col;
        Gs[r  ][col  ] = acc[mf][0] + xg0[0];
        Gs[r  ][col+1] = acc[mf][1] + xg0[1];
        Gs[r+8][col  ] = acc[mf][2] + xg1[0];
        Gs[r+8][col+1] = acc[mf][3] + xg1[1];
    }
    __syncthreads();

    // combine gates -> c_t, h_t (512 (row, j) pairs, 4 per thread)
    const int j0 = p0 >> 2;
#pragma unroll
    for (int q=0;q<4;++q){
        int it = tid + (q<<7);
        int r = it >> 3, jj = it & 7;
        float gf = Gs[r][(jj<<2)+0];
        float gi = Gs[r][(jj<<2)+1];
        float gc = Gs[r][(jj<<2)+2];
        float go = Gs[r][(jj<<2)+3];
        float f = 1.f/(1.f + expf(-gf));
        float i = 1.f/(1.f + expf(-gi));
        float cand = tanhf(gc);
        float o = 1.f/(1.f + expf(-go));
        int jg = j0 + jj;
        float cp = cprev[(size_t)r*HH + jg];
        float cn = f*cp + i*cand;
        float hn = o*tanhf(cn);
        cout[(size_t)r*HH + jg] = cn;
        hout[(size_t)r*HH + jg] = hn;
    }
}

// ---------------------------------------------------------------------------
// GEMM C: Y[m, v] = sum_k all_h[m, k] * Wout[k, v] + bout[v]
// M=16384, N=10000, K=1024. Same structure, N bounds-checked.
// ---------------------------------------------------------------------------
__global__ __launch_bounds__(256) void gemm_out(const float* __restrict__ Hall,
                                                const float* __restrict__ Wout,
                                                const float* __restrict__ bout,
                                                float* __restrict__ Y){
    __shared__ float As[128][36];
    __shared__ float Bs[32][132];
    const int m0 = blockIdx.y << 7;
    const int n0 = blockIdx.x << 7;
    const int tid = threadIdx.x;
    const int w = tid >> 5, lane = tid & 31;
    const int g = lane >> 2, qi = lane & 3;
    const int wm = (w & 1) << 6, wn = (w >> 1) << 5;

    float acc[4][4][4];
#pragma unroll
    for (int a=0;a<4;++a)
#pragma unroll
    for (int b=0;b<4;++b)
#pragma unroll
    for (int c2=0;c2<4;++c2) acc[a][b][c2] = 0.f;

    int arow[4], akv[4];
    const float* aptr[4];
#pragma unroll
    for (int q=0;q<4;++q){
        int fi = tid + (q<<8);
        arow[q] = fi >> 3; akv[q] = fi & 7;
        aptr[q] = Hall + (size_t)(m0 + arow[q])*HH + (akv[q]<<2);
    }
    int bkk[4], bnv[4];
    const float* bptr[4];
    bool bok[4];
#pragma unroll
    for (int q=0;q<4;++q){
        int fi = tid + (q<<8);
        bkk[q] = fi >> 5; bnv[q] = fi & 31;
        bok[q] = (n0 + (bnv[q]<<2)) < VV;
        bptr[q] = Wout + (size_t)bkk[q]*VV + n0 + (bnv[q]<<2);
    }
    float4 ar[4], br[4];
    const float4 z4 = make_float4(0.f,0.f,0.f,0.f);
#pragma unroll
    for (int q=0;q<4;++q) ar[q] = *(const float4*)aptr[q];
#pragma unroll
    for (int q=0;q<4;++q) br[q] = bok[q] ? *(const float4*)bptr[q] : z4;

    const int KT = HH/32;  // 32
    for (int kt = 0; kt < KT; ++kt){
#pragma unroll
        for (int q=0;q<4;++q){
            uint4 u; u.x=f2tf(ar[q].x); u.y=f2tf(ar[q].y); u.z=f2tf(ar[q].z); u.w=f2tf(ar[q].w);
            *reinterpret_cast<uint4*>(&As[arow[q]][akv[q]<<2]) = u;
        }
#pragma unroll
        for (int q=0;q<4;++q){
            uint4 u; u.x=f2tf(br[q].x); u.y=f2tf(br[q].y); u.z=f2tf(br[q].z); u.w=f2tf(br[q].w);
            *reinterpret_cast<uint4*>(&Bs[bkk[q]][bnv[q]<<2]) = u;
        }
        __syncthreads();
        if (kt+1 < KT){
#pragma unroll
            for (int q=0;q<4;++q) ar[q] = *(const float4*)(aptr[q] + (kt+1)*32);
#pragma unroll
            for (int q=0;q<4;++q) br[q] = bok[q] ? *(const float4*)(bptr[q] + (size_t)(kt+1)*32*VV) : z4;
        }
#pragma unroll
        for (int ks=0; ks<4; ++ks){
            const int kb = ks<<3;
            unsigned af[4][4];
#pragma unroll
            for (int mf=0; mf<4; ++mf){
                int r = wm + (mf<<4) + g;
                af[mf][0] = __float_as_uint(As[r  ][kb+qi]);
                af[mf][1] = __float_as_uint(As[r+8][kb+qi]);
                af[mf][2] = __float_as_uint(As[r  ][kb+qi+4]);
                af[mf][3] = __float_as_uint(As[r+8][kb+qi+4]);
            }
            unsigned bfr[4][2];
#pragma unroll
            for (int nf=0; nf<4; ++nf){
                int cc = wn + (nf<<3) + g;
                bfr[nf][0] = __float_as_uint(Bs[kb+qi  ][cc]);
                bfr[nf][1] = __float_as_uint(Bs[kb+qi+4][cc]);
            }
#pragma unroll
            for (int mf=0; mf<4; ++mf)
#pragma unroll
            for (int nf=0; nf<4; ++nf)
                mma_tf32(acc[mf][nf], af[mf], bfr[nf]);
        }
        __syncthreads();
    }
#pragma unroll
    for (int mf=0; mf<4; ++mf){
        int r0 = m0 + wm + (mf<<4) + g;
#pragma unroll
        for (int nf=0; nf<4; ++nf){
            int col = n0 + wn + (nf<<3) + (qi<<1);
            if (col < VV){   // col is even, VV even -> col+1 also valid
                float b0 = bout[col], b1 = bout[col+1];
                float* d0 = Y + (size_t)r0*VV + col;
                float* d1 = Y + (size_t)(r0+8)*VV + col;
                d0[0] = acc[mf][nf][0] + b0;
                d0[1] = acc[mf][nf][1] + b1;
                d1[0] = acc[mf][nf][2] + b0;
                d1[1] = acc[mf][nf][3] + b1;
            }
        }
    }
}

// ---------------------------------------------------------------------------
// Launch: pack -> x-projection GEMM -> 256 sequential step kernels -> output GEMM
// d_out layout (float32): all_h [T,B,H] | all_c [T,B,H] | all_y [T,B,V]
// ---------------------------------------------------------------------------
extern "C" void kernel_launch(void* const* d_in, const int* in_sizes, int n_in,
                              void* d_out, int out_size){
    (void)in_sizes; (void)n_in; (void)out_size;
    const int*   x      = (const int*)  d_in[0];
    const float* h_in   = (const float*)d_in[1];
    const float* c_in   = (const float*)d_in[2];
    const float* emb    = (const float*)d_in[3];
    const float* Wf_w   = (const float*)d_in[4];
    const float* Wf_b   = (const float*)d_in[5];
    const float* Wi_w   = (const float*)d_in[6];
    const float* Wi_b   = (const float*)d_in[7];
    const float* Wc_w   = (const float*)d_in[8];
    const float* Wc_b   = (const float*)d_in[9];
    const float* Wo_w   = (const float*)d_in[10];
    const float* Wo_b   = (const float*)d_in[11];
    const float* Wout_w = (const float*)d_in[12];
    const float* Wout_b = (const float*)d_in[13];
    float* out = (float*)d_out;

    pack_kernel<<<256, 256>>>(Wf_w, Wi_w, Wc_w, Wo_w, Wf_b, Wi_b, Wc_b, Wo_b);

    gemm_xproj<<<dim3(NG/128, MALL/128), 256>>>(x, emb);

    for (int t = 0; t < TT; ++t)
        step_kernel<<<NG/32, 128>>>(t, h_in, c_in, out);

    gemm_out<<<dim3((VV + 127)/128, MALL/128), 256>>>(out, Wout_w, Wout_b, out + YBASE);
}